// round 14
// baseline (speedup 1.0000x reference)
#include <cuda_runtime.h>
#include <cuda_bf16.h>

#define S 128
#define TSTR 136   // tile row stride (floats); k>=64 skewed +4 (mid-row pad)
#define PS 132     // p buffer stride: slot(k) = k + (k>=64 ? 4 : 0)
#define NCTA 296   // persistent: 2 CTAs per SM
#define NTILE 2048

__device__ __align__(16) unsigned g_mrow[16 * S * 4];  // bit j: mask[b,i,j]
__device__ __align__(16) unsigned g_span[16 * S * 4];  // bit k: mask[b,j,k] | mask[b,k,j]

__device__ __forceinline__ float sigmoidf_(float x) {
    return 1.0f / (1.0f + __expf(-x));
}
__device__ __forceinline__ unsigned smem_u32(const void* p) {
    unsigned r;
    asm("{ .reg .u64 t; cvta.to.shared.u64 t, %1; cvt.u32.u64 %0, t; }" : "=r"(r) : "l"(p));
    return r;
}
#define CP_ASYNC16(dst, src) \
    asm volatile("cp.async.cg.shared.global [%0], [%1], 16;\n" :: "r"(dst), "l"(src))
#define CP_COMMIT() asm volatile("cp.async.commit_group;\n")
#define CP_WAIT0()  asm volatile("cp.async.wait_group 0;\n")

#define FMA2(acc, a, b) \
    asm("fma.rn.f32x2 %0, %1, %2, %3;" : "=l"(acc) : "l"(a), "l"(b), "l"(acc))
#define PACK2(d, x, y) \
    asm("mov.b64 %0, {%1, %2};" : "=l"(d) : "f"(x), "f"(y))
#define UNPACK2(x, y, d) \
    asm("mov.b64 {%0, %1}, %2;" : "=f"(x), "=f"(y) : "l"(d))

__device__ __forceinline__ unsigned pick_word(uint4 v, int wd) {
    return (wd == 0) ? v.x : (wd == 1) ? v.y : (wd == 2) ? v.z : v.w;
}
__device__ __forceinline__ int popc4(uint4 v) {
    return __popc(v.x) + __popc(v.y) + __popc(v.z) + __popc(v.w);
}
// position of the (rem+1)-th set bit in a 32-bit word (rem 0-based; caller guarantees it exists)
__device__ __forceinline__ int nth_set_word(unsigned word, int rem) {
    int pos = 0, c;
    c = __popc(word & 0xFFFFu); if (rem >= c) { rem -= c; pos = 16; word >>= 16; }
    c = __popc(word & 0xFFu);   if (rem >= c) { rem -= c; pos += 8; word >>= 8; }
    c = __popc(word & 0xFu);    if (rem >= c) { rem -= c; pos += 4; word >>= 4; }
    c = __popc(word & 0x3u);    if (rem >= c) { rem -= c; pos += 2; word >>= 2; }
    c = (int)(word & 1u);       if (rem >= c) { pos += 1; }
    return pos;
}
// row index of compacted slot s in 128-bit mask v (caller guarantees s < popc4(v))
__device__ __forceinline__ int nth_set128(uint4 v, int s) {
    int c0 = __popc(v.x), c1 = c0 + __popc(v.y), c2 = c1 + __popc(v.z);
    unsigned word; int base, rem;
    if (s < c0)      { word = v.x; base = 0;  rem = s; }
    else if (s < c1) { word = v.y; base = 32; rem = s - c0; }
    else if (s < c2) { word = v.z; base = 64; rem = s - c1; }
    else             { word = v.w; base = 96; rem = s - c2; }
    return base + nth_set_word(word, rem);
}
__device__ __forceinline__ int slotf(int k) { return k + ((k >= 64) ? 4 : 0); }

// ---- Pre-kernel: pack masks to bits; grid (16 batches x 4 j-quarters) ----
__global__ __launch_bounds__(512)
void mask_pack_kernel(const int* __restrict__ mask) {
    __shared__ unsigned char m[S * 132];
    const int b  = blockIdx.x;
    const int qy = blockIdx.y;
    const int t  = threadIdx.x;
    const int4* mg = reinterpret_cast<const int4*>(mask + (size_t)b * S * S);
    #pragma unroll
    for (int n = 0; n < 8; n++) {
        int idx = n * 512 + t;
        int row = idx >> 5, c4 = idx & 31;
        int4 v = __ldg(mg + idx);
        uchar4 u;
        u.x = (unsigned char)(v.x != 0); u.y = (unsigned char)(v.y != 0);
        u.z = (unsigned char)(v.z != 0); u.w = (unsigned char)(v.w != 0);
        *reinterpret_cast<uchar4*>(&m[row * 132 + (c4 << 2)]) = u;
    }
    __syncthreads();
    const int w = t >> 5, lane = t & 31;
    for (int task = w; task < 128; task += 16) {
        const int j  = (qy << 5) + (task >> 2);
        const int wd = task & 3;
        const int k  = (wd << 5) + lane;
        unsigned mjk = m[j * 132 + k];
        unsigned mkj = m[k * 132 + j];
        unsigned rw = __ballot_sync(0xffffffffu, mjk != 0);
        unsigned sw = __ballot_sync(0xffffffffu, (mjk | mkj) != 0);
        if (lane == 0) {
            g_mrow[(b * S + j) * 4 + wd] = rw;
            g_span[(b * S + j) * 4 + wd] = sw;
        }
    }
}

// ---- Main: persistent CTAs, warp-private load/readback/prefetch, 3 bars/tile ----
extern __shared__ float sm[];

__global__ __launch_bounds__(256, 2)
void mfvi_main(const float* __restrict__ s_span,
               const float* __restrict__ s_pair,
               float* __restrict__ out)
{
    float* tile = sm;                    // S * TSTR floats (compacted live rows)
    float* pA   = sm + S * TSTR;
    float* pB   = pA + PS;

    const int t    = threadIdx.x;
    const int lane = t & 31;
    const int w    = t >> 5;             // warp 0..7
    const int lr   = t >> 1;             // compacted slot this thread consumes (= 16w + (lane>>1))
    const int h2   = t & 1;              // k-half
    const int cb   = h2 * 68;            // skewed column base

    const unsigned tb  = smem_u32(tile);
    const int co  = lane << 2;
    const int dco = co + ((lane >= 16) ? 4 : 0);

    // ---- prologue: tile n's slot->row map (registers) + loads (warp-private) ----
    int n = blockIdx.x;
    uint4 mr = *reinterpret_cast<const uint4*>(&g_mrow[((n >> 7) * S + (n & 127)) * 4]);
    int Lcur = popc4(mr);
    int myrow = 0;                        // lane l<16 holds row of slot 16w+l
    if (lane < 16 && ((w << 4) + lane) < Lcur)
        myrow = nth_set128(mr, (w << 4) + lane);
    #pragma unroll
    for (int ii = 0; ii < 16; ii++) {
        const int s = (w << 4) + ii;
        const int r = __shfl_sync(0xffffffffu, myrow, ii);
        if (s < Lcur)
            CP_ASYNC16(tb + (unsigned)((s * TSTR + dco) << 2),
                       s_pair + ((size_t)n * S + (size_t)r) * S + co);
    }
    CP_COMMIT();

    float* pa = pA;
    float* pb = pB;

    for (; n < NTILE; n += NCTA) {
        const int b = n >> 7;
        const int i = n & 127;
        const int nn = n + NCTA;
        uint4 mr_next = make_uint4(0u, 0u, 0u, 0u);
        if (nn < NTILE)
            mr_next = *reinterpret_cast<const uint4*>(
                &g_mrow[((nn >> 7) * S + (nn & 127)) * 4]);
        const int Lnext = popc4(mr_next);
        int myrow_next = 0;
        if (lane < 16 && ((w << 4) + lane) < Lnext)
            myrow_next = nth_set128(mr_next, (w << 4) + lane);

        // ---- scalar phase (overlaps current tile's DRAM) ----
        bool  deadr = false;
        float pvv   = 0.f;
        if (t < S) {
            float v = __ldg(&s_span[(size_t)n * S + t]);
            pvv = sigmoidf_(v);
            pa[slotf(t)] = pvv;                       // p0 for ALL rows
            if (!((pick_word(mr, t >> 5) >> (t & 31)) & 1u)) {
                deadr = true;
                out[(size_t)n * S + t] = pvv;         // dead row: final output now
            }
        }
        // compute mapping for this thread's slot (register shfl, no smem)
        const bool act = lr < Lcur;
        const int  j   = __shfl_sync(0xffffffffu, myrow, lane >> 1);
        float ssj = 0.f; unsigned em0 = 0u, em1 = 0u;
        if (act) {
            if (h2 == 0) ssj = __ldg(&s_span[(size_t)n * S + j]);
            em0 = __ldg(&g_span[(b * S + j) * 4 + (h2 << 1) + 0]);
            em1 = __ldg(&g_span[(b * S + j) * 4 + (h2 << 1) + 1]);
            const int lo = min(i, j), hi = max(i, j);
            if ((lo >> 5) == (h2 << 1))     em0 &= ~(1u << (lo & 31));
            if ((lo >> 5) == (h2 << 1) + 1) em1 &= ~(1u << (lo & 31));
            if ((hi >> 5) == (h2 << 1))     em0 &= ~(1u << (hi & 31));
            if ((hi >> 5) == (h2 << 1) + 1) em1 &= ~(1u << (hi & 31));
        }

        CP_WAIT0();   // WARP-LOCAL: my own slots landed (no CTA barrier)

        // ---- readback + mask + pack (warp-private slots) ----
        unsigned long long M2[32];
        if (act) {
            #pragma unroll
            for (int q = 0; q < 16; q++) {
                float4 v = *reinterpret_cast<const float4*>(&tile[lr * TSTR + cb + (q << 2)]);
                const unsigned em = (q < 8) ? em0 : em1;
                const int sh = (q << 2) & 31;
                v.x = ((em >> (sh + 0)) & 1u) ? v.x : 0.f;
                v.y = ((em >> (sh + 1)) & 1u) ? v.y : 0.f;
                v.z = ((em >> (sh + 2)) & 1u) ? v.z : 0.f;
                v.w = ((em >> (sh + 3)) & 1u) ? v.w : 0.f;
                PACK2(M2[2*q],   v.x, v.y);
                PACK2(M2[2*q+1], v.z, v.w);
            }
        }

        // ---- issue next tile's loads into MY slots (warp-private, LSU-ordered) ----
        #pragma unroll
        for (int ii = 0; ii < 16; ii++) {
            const int s = (w << 4) + ii;
            const int r = __shfl_sync(0xffffffffu, myrow_next, ii);
            if (s < Lnext)
                CP_ASYNC16(tb + (unsigned)((s * TSTR + dco) << 2),
                           s_pair + ((size_t)nn * S + (size_t)r) * S + co);
        }
        CP_COMMIT();

        __syncthreads();   // bar_pre: p0 (pa) visible to all it0 readers

        if (deadr) pb[slotf(t)] = pvv;   // it1 readers of pb are bar2-protected

        // ---- 3 MFVI iterations; warp-prefix shfl masks ----
        const int pairsw = min(max(Lcur - (w << 4), 0), 16);
        const unsigned smask = (pairsw >= 16) ? 0xffffffffu
                             : ((pairsw <= 0) ? 0u : ((1u << (pairsw << 1)) - 1u));
        #pragma unroll
        for (int it = 0; it < 3; it++) {
            const float* pr = (it & 1) ? pb : pa;
            float*       pw = (it & 1) ? pa : pb;
            if (act) {
                unsigned long long a0 = 0ull, a1 = 0ull, a2 = 0ull, a3 = 0ull;
                #pragma unroll
                for (int q = 0; q < 16; q += 2) {
                    ulonglong2 pv0 = *reinterpret_cast<const ulonglong2*>(&pr[cb + (q << 2)]);
                    ulonglong2 pv1 = *reinterpret_cast<const ulonglong2*>(&pr[cb + ((q + 1) << 2)]);
                    FMA2(a0, pv0.x, M2[2*q]);
                    FMA2(a1, pv0.y, M2[2*q+1]);
                    FMA2(a2, pv1.x, M2[2*q+2]);
                    FMA2(a3, pv1.y, M2[2*q+3]);
                }
                float x0, x1, y0, y1, z0, z1, w0, w1;
                UNPACK2(x0, x1, a0);
                UNPACK2(y0, y1, a1);
                UNPACK2(z0, z1, a2);
                UNPACK2(w0, w1, a3);
                float acc = ((x0 + x1) + (y0 + y1)) + ((z0 + z1) + (w0 + w1));
                acc += __shfl_xor_sync(smask, acc, 1);
                if (h2 == 0) {
                    if (it < 2) pw[slotf(j)] = sigmoidf_(ssj + acc);
                    else        out[(size_t)n * S + j] = sigmoidf_(ssj + acc);
                }
            }
            if (it < 2) __syncthreads();   // bars 2,3
            // it==2: no barrier — next tile's p-init writes the rotated buffer
        }

        // rotate per-tile state
        { float* tp = pa; pa = pb; pb = tp; }
        mr = mr_next;
        Lcur = Lnext;
        myrow = myrow_next;
    }
}

extern "C" void kernel_launch(void* const* d_in, const int* in_sizes, int n_in,
                              void* d_out, int out_size) {
    const float* s_span = (const float*)d_in[0];
    const float* s_pair = (const float*)d_in[1];
    const int*   mask   = (const int*)d_in[2];
    float* out = (float*)d_out;

    const int smem_bytes = (S * TSTR + 2 * PS) * sizeof(float);  // ~70.7 KB
    cudaFuncSetAttribute(mfvi_main, cudaFuncAttributeMaxDynamicSharedMemorySize, smem_bytes);

    dim3 pg(16, 4);
    mask_pack_kernel<<<pg, 512>>>(mask);
    mfvi_main<<<NCTA, 256, smem_bytes>>>(s_span, s_pair, out);
}